// round 11
// baseline (speedup 1.0000x reference)
#include <cuda_runtime.h>
#include <cstdint>

#define Bb  2
#define Pp  128
#define Cc  8
#define Hh  16
#define Gg  4
#define Dd  64
#define Ee  1024
#define EKVv 256
#define Tt  1024

// ---------------- scratch (device globals; no allocation allowed) -----------
__device__ __align__(16) float g_q[Bb*Tt*Ee];
__device__ __align__(16) float g_kv[Bb*Tt*2*EKVv];
__device__ __align__(16) float g_tk[Pp*EKVv];
__device__ __align__(16) float g_ck[Cc*EKVv];
__device__ __align__(16) float g_time[Bb*Hh*Tt*Pp];
__device__ __align__(16) float g_chan[Bb*Hh*Tt*Cc];
__device__ __align__(16) float g_ao[Bb*Tt*Ee];

// ---------------- packed f32x2 + cp.async helpers ----------------------------
__device__ __forceinline__ unsigned long long dup2(float x) {
    unsigned long long r;
    asm("mov.b64 %0, {%1, %1};" : "=l"(r) : "f"(x));
    return r;
}
__device__ __forceinline__ void fma2(unsigned long long& d,
                                     unsigned long long a, unsigned long long b) {
    asm("fma.rn.f32x2 %0, %1, %2, %0;" : "+l"(d) : "l"(a), "l"(b));
}
__device__ __forceinline__ uint32_t smem_u32(const void* p) {
    uint32_t a;
    asm("{ .reg .u64 t; cvta.to.shared.u64 t, %1; cvt.u32.u64 %0, t; }"
        : "=r"(a) : "l"(p));
    return a;
}
__device__ __forceinline__ void cp16(uint32_t s, const void* g) {
    asm volatile("cp.async.cg.shared.global [%0], [%1], 16;" :: "r"(s), "l"(g));
}
#define CP_COMMIT() asm volatile("cp.async.commit_group;" ::: "memory")
#define CP_WAIT0()  asm volatile("cp.async.wait_group 0;" ::: "memory")

// ---------------- 128x128 fp32 GEMM tile body (cp.async dbl-buffer, FMA2) ----
// As layout [m][k] so cp.async can fill it; A read via broadcast LDS.
__device__ __forceinline__ void gemm128_body(
        const float* __restrict__ A, const float* __restrict__ B,
        float* __restrict__ Cmat, int N, int K, int m0, int n0,
        float (*As)[128][8], float (*Bs)[8][128]) {
    int tid = threadIdx.x;
    int tx = tid & 15, ty = tid >> 4;
    int arow = tid >> 1, akq = (tid & 1) * 4;
    int brow = tid >> 5, bnq = (tid & 31) * 4;

    const float* Aptr = A + (size_t)(m0 + arow) * K + akq;
    const float* Bptr = B + (size_t)brow * N + n0 + bnq;
    uint32_t sA0 = smem_u32(&As[0][arow][akq]);
    uint32_t sA1 = smem_u32(&As[1][arow][akq]);
    uint32_t sB0 = smem_u32(&Bs[0][brow][bnq]);
    uint32_t sB1 = smem_u32(&Bs[1][brow][bnq]);

    unsigned long long acc2[8][4];
#pragma unroll
    for (int i = 0; i < 8; i++)
#pragma unroll
        for (int j = 0; j < 4; j++) acc2[i][j] = 0ull;

    // prologue: stage tile 0
    cp16(sA0, Aptr);
    cp16(sB0, Bptr);
    CP_COMMIT();
    CP_WAIT0();
    __syncthreads();

    int NT = K >> 3;
    int cur = 0;
    for (int kt = 0; kt < NT; kt++) {
        if (kt + 1 < NT) {
            cp16(cur ? sA0 : sA1, Aptr + (kt + 1) * 8);
            cp16(cur ? sB0 : sB1, Bptr + (size_t)(kt + 1) * 8 * N);
            CP_COMMIT();
        }
#pragma unroll
        for (int k = 0; k < 8; k++) {
            float a_sc[8];
#pragma unroll
            for (int i = 0; i < 8; i++) a_sc[i] = As[cur][ty * 8 + i][k];
            ulonglong2 bl0 = *(const ulonglong2*)&Bs[cur][k][tx * 8];
            ulonglong2 bl1 = *(const ulonglong2*)&Bs[cur][k][tx * 8 + 4];
            unsigned long long rb2[4] = {bl0.x, bl0.y, bl1.x, bl1.y};
#pragma unroll
            for (int i = 0; i < 8; i++) {
                unsigned long long a2 = dup2(a_sc[i]);
#pragma unroll
                for (int j = 0; j < 4; j++) fma2(acc2[i][j], a2, rb2[j]);
            }
        }
        if (kt + 1 < NT) {
            CP_WAIT0();
            __syncthreads();
            cur ^= 1;
        }
    }

#pragma unroll
    for (int i = 0; i < 8; i++) {
        float* crow = Cmat + (size_t)(m0 + ty * 8 + i) * N + n0 + tx * 8;
        *(ulonglong2*)crow       = make_ulonglong2(acc2[i][0], acc2[i][1]);
        *(ulonglong2*)(crow + 4) = make_ulonglong2(acc2[i][2], acc2[i][3]);
    }
}

// ---------------- skinny row GEMM: C[m, n0:+128], intra-block split-K --------
__device__ __forceinline__ void skinny_body(
        const float* __restrict__ A, const float* __restrict__ B,
        float* __restrict__ C, int N, int K, int m, int n0) {
    __shared__ float red[128];
    int t = threadIdx.x;
    int n = n0 + (t & 127);
    int kc = t >> 7;
    int kh = K >> 1;
    const float* a = A + (size_t)m * K + kc * kh;
    const float* b = B + (size_t)(kc * kh) * N + n;
    float acc = 0.f;
#pragma unroll 8
    for (int k = 0; k < kh; k++) acc += a[k] * b[(size_t)k * N];
    if (kc) red[t & 127] = acc;
    __syncthreads();
    if (!kc) C[(size_t)m * N + n] = acc + red[t & 127];
}

// ---------------- one launch for ALL projections ------------------------------
// blocks: [0,128) q | [128,192) kv | [192,448) tk | [448,464) ck
__global__ __launch_bounds__(256, 2) void mega_gemm(
        const float* __restrict__ hs, const float* __restrict__ Wq,
        const float* __restrict__ Wkv,
        const float* __restrict__ pe, const float* __restrict__ Wpos,
        const float* __restrict__ ce, const float* __restrict__ Wchan,
        float* __restrict__ q, float* __restrict__ kv,
        float* __restrict__ tk, float* __restrict__ ck) {
    __shared__ float As[2][128][8];
    __shared__ float Bs[2][8][128];
    int blk = blockIdx.x;
    if (blk < 128) {
        gemm128_body(hs, Wq, q, Ee, Ee, (blk >> 3) * 128, (blk & 7) * 128, As, Bs);
    } else if (blk < 192) {
        int b = blk - 128;
        gemm128_body(hs, Wkv, kv, 2 * EKVv, Ee, (b >> 2) * 128, (b & 3) * 128, As, Bs);
    } else if (blk < 448) {
        int b = blk - 192;
        skinny_body(pe, Wpos, tk, EKVv, Ee, b >> 1, (b & 1) * 128);
    } else {
        int b = blk - 448;
        skinny_body(ce, Wchan, ck, EKVv, Ee, b >> 1, (b & 1) * 128);
    }
}

// ---------------- standalone GEMM for the output projection ------------------
__global__ __launch_bounds__(256, 2) void sgemm128(
        const float* __restrict__ A, const float* __restrict__ B,
        float* __restrict__ Cmat, int N, int K) {
    __shared__ float As[2][128][8];
    __shared__ float Bs[2][8][128];
    gemm128_body(A, B, Cmat, N, K, blockIdx.y * 128, blockIdx.x * 128, As, Bs);
}

// ---------------- merged time_att + chan_att ---------------------------------
__global__ __launch_bounds__(256) void rel_att_kernel(
        const float* __restrict__ q, const float* __restrict__ bias) {
    __shared__ float qs[32][65];
    __shared__ float ks[128][64];
    int blk = blockIdx.x;
    int tid = threadIdx.x;
    if (blk < 1024) {
        int bh = blk & 31;
        int b = bh / Hh, h = bh % Hh, kvh = h / Gg;
        int t0 = (blk >> 5) * 32;
        for (int i = tid; i < 32 * 64; i += 256) {
            int r = i >> 6, d = i & 63;
            qs[r][d] = q[((size_t)(b * Tt + t0 + r)) * Ee + h * Dd + d]
                     + bias[EKVv + kvh * Dd + d];
        }
        for (int i = tid; i < 128 * 64; i += 256) {
            int p = i >> 6, d = i & 63;
            ks[p][d] = g_tk[p * EKVv + kvh * Dd + d];
        }
        __syncthreads();
        int r = tid & 31;
        int pb = (tid >> 5) * 16;
        float acc[16];
#pragma unroll
        for (int j = 0; j < 16; j++) acc[j] = 0.f;
        for (int d = 0; d < 64; d++) {
            float qv = qs[r][d];
#pragma unroll
            for (int j = 0; j < 16; j++) acc[j] += qv * ks[pb + j][d];
        }
        float* dst = g_time + ((size_t)bh * Tt + t0 + r) * Pp + pb;
#pragma unroll
        for (int j = 0; j < 16; j++) dst[j] = acc[j];
    } else {
        int bc = blk - 1024;
        int bh = bc & 31;
        int b = bh / Hh, h = bh % Hh, kvh = h / Gg;
        int t0 = (bc >> 5) * 32;
        for (int i = tid; i < 32 * 64; i += 256) {
            int r = i >> 6, d = i & 63;
            qs[r][d] = q[((size_t)(b * Tt + t0 + r)) * Ee + h * Dd + d]
                     + bias[2 * EKVv + kvh * Dd + d];
        }
        for (int i = tid; i < 8 * 64; i += 256) {
            int c = i >> 6, d = i & 63;
            ks[c][d] = g_ck[c * EKVv + kvh * Dd + d];
        }
        __syncthreads();
        int r = tid >> 3, c = tid & 7;
        float acc = 0.f;
#pragma unroll
        for (int d = 0; d < 64; d++) acc += qs[r][d] * ks[c][d];
        g_chan[((size_t)bh * Tt + t0 + r) * Cc + c] = acc;
    }
}

// ---------------- attention core: one block per (b, h, pt) -------------------
__global__ __launch_bounds__(256) void attn_kernel(
        const float* __restrict__ q, const float* __restrict__ bias) {
    __shared__ float qg[8][65];
    __shared__ float lg[8][1025];
    __shared__ float rinv[8];
    __shared__ float sred[8][8][64];
    int blk = blockIdx.x;
    int pt = (Pp - 1) - (blk % Pp);              // big-S blocks first
    int h  = (blk / Pp) % Hh;
    int b  = blk / (Pp * Hh);
    int kvh = h / Gg;
    int tid = threadIdx.x;
    int t0 = pt * Cc;

    for (int i = tid; i < 8 * 64; i += 256) {
        int c = i >> 6, d = i & 63;
        qg[c][d] = q[((size_t)(b * Tt + t0 + c)) * Ee + h * Dd + d]
                 + bias[kvh * Dd + d];
    }
    __syncthreads();

    int S = (pt + 1) * Cc;
    const float* tbase = g_time + (size_t)(b * Hh + h) * Tt * Pp;
    const float* cbase = g_chan + (size_t)(b * Hh + h) * Tt * Cc;

    // base logits, s-fastest mapping: lane-consecutive s0 -> coalesced tbase
    for (int s0 = tid; s0 < S; s0 += 256) {
        int ps = s0 >> 3, cs = s0 & 7;
#pragma unroll
        for (int c = 0; c < 8; c++) {
            int t = t0 + c;
            unsigned m = (unsigned)(t + 1) * Pp + ps;
            unsigned i2 = m / (Tt + 1);
            float tv = 0.f;
            if (m - i2 * (Tt + 1) != 0) tv = tbase[m - i2 - 1];
            int dc = c - cs; dc = dc < 0 ? -dc : dc;
            float cv = cbase[t * Cc + (Cc - 1 - dc)];
            lg[c][s0] = tv + cv;
        }
    }
    __syncthreads();

    // global term only inside the wm band (last patch row: everywhere)
    int gLow = (pt == Pp - 1) ? 0 : ((pt > 10 ? pt - 10 : 0) * Cc);
    int nG = (S - gLow) * 8;
    for (int idx = tid; idx < nG; idx += 256) {
        int s = gLow + (idx >> 3);
        int c = idx & 7;
        const float4* gk4 = (const float4*)(g_kv
            + ((size_t)(b * Tt + s)) * (2 * EKVv) + kvh * Dd);
        float acc = 0.f;
#pragma unroll
        for (int d4 = 0; d4 < 16; d4++) {
            float4 gv = gk4[d4];
            acc += qg[c][d4 * 4 + 0] * gv.x + qg[c][d4 * 4 + 1] * gv.y
                 + qg[c][d4 * 4 + 2] * gv.z + qg[c][d4 * 4 + 3] * gv.w;
        }
        lg[c][s] += acc;
    }
    __syncthreads();

    // softmax: warp w owns row w
    int w = tid >> 5, lane = tid & 31;
    {
        float mx = -1e30f;
        for (int s = lane; s < S; s += 32) mx = fmaxf(mx, lg[w][s] * 0.125f);
#pragma unroll
        for (int o = 16; o > 0; o >>= 1)
            mx = fmaxf(mx, __shfl_xor_sync(0xffffffffu, mx, o));
        float sum = 0.f;
        for (int s = lane; s < S; s += 32) {
            float e = __expf(lg[w][s] * 0.125f - mx);
            lg[w][s] = e;
            sum += e;
        }
#pragma unroll
        for (int o = 16; o > 0; o >>= 1)
            sum += __shfl_xor_sync(0xffffffffu, sum, o);
        if (lane == 0) rinv[w] = 1.f / sum;
    }
    __syncthreads();

    // out[c,d] = sum_s w[c,s]*v[s,d]; v loaded once per (s, d-pair)
    {
        int dp = (tid & 31) * 2;
        int sg = tid >> 5;
        const float* vbase = g_kv + (size_t)b * Tt * (2 * EKVv) + EKVv
                           + kvh * Dd + dp;
        float accx[8], accy[8];
#pragma unroll
        for (int c = 0; c < 8; c++) { accx[c] = 0.f; accy[c] = 0.f; }
        for (int s = sg; s < S; s += 8) {
            float2 vv = *(const float2*)(vbase + (size_t)s * (2 * EKVv));
#pragma unroll
            for (int c = 0; c < 8; c++) {
                float wgt = lg[c][s];
                accx[c] += wgt * vv.x;
                accy[c] += wgt * vv.y;
            }
        }
#pragma unroll
        for (int c = 0; c < 8; c++) {
            sred[sg][c][dp]     = accx[c];
            sred[sg][c][dp + 1] = accy[c];
        }
    }
    __syncthreads();
    for (int i = tid; i < 512; i += 256) {
        int c = i >> 6, dd = i & 63;
        float o = ((sred[0][c][dd] + sred[1][c][dd])
                 + (sred[2][c][dd] + sred[3][c][dd]))
                + ((sred[4][c][dd] + sred[5][c][dd])
                 + (sred[6][c][dd] + sred[7][c][dd]));
        g_ao[((size_t)(b * Tt + t0 + c)) * Ee + h * Dd + dd] = o * rinv[c];
    }
}

// ---------------- launch ----------------------------------------------------
extern "C" void kernel_launch(void* const* d_in, const int* in_sizes, int n_in,
                              void* d_out, int out_size) {
    const float* hs    = (const float*)d_in[0];
    const float* pe    = (const float*)d_in[1];
    const float* ce    = (const float*)d_in[2];
    const float* Wq    = (const float*)d_in[3];
    const float* Wkv   = (const float*)d_in[4];
    const float* Wpos  = (const float*)d_in[5];
    const float* Wchan = (const float*)d_in[6];
    const float* Wproj = (const float*)d_in[7];
    const float* bias  = (const float*)d_in[8];

    float *q, *kv, *tk, *ck, *ao;
    cudaGetSymbolAddress((void**)&q,  g_q);
    cudaGetSymbolAddress((void**)&kv, g_kv);
    cudaGetSymbolAddress((void**)&tk, g_tk);
    cudaGetSymbolAddress((void**)&ck, g_ck);
    cudaGetSymbolAddress((void**)&ao, g_ao);

    // all projections in one chip-filling launch
    mega_gemm<<<464, 256>>>(hs, Wq, Wkv, pe, Wpos, ce, Wchan, q, kv, tk, ck);

    // relative logits (time + chan merged)
    rel_att_kernel<<<2048, 256>>>(q, bias);

    // attention core
    attn_kernel<<<Bb * Hh * Pp, 256>>>(q, bias);

    // output projection -> d_out
    sgemm128<<<dim3(Ee / 128, (Bb * Tt) / 128), 256>>>(ao, Wproj, (float*)d_out, Ee, Ee);
}

// round 12
// speedup vs baseline: 1.0821x; 1.0821x over previous
#include <cuda_runtime.h>

#define Bb  2
#define Pp  128
#define Cc  8
#define Hh  16
#define Gg  4
#define Dd  64
#define Ee  1024
#define EKVv 256
#define Tt  1024

// ---------------- scratch (device globals; no allocation allowed) -----------
__device__ __align__(16) float g_q[Bb*Tt*Ee];
__device__ __align__(16) float g_kv[Bb*Tt*2*EKVv];
__device__ __align__(16) float g_tk[Pp*EKVv];
__device__ __align__(16) float g_ck[Cc*EKVv];
__device__ __align__(16) float g_time[Bb*Hh*Tt*Pp];
__device__ __align__(16) float g_chan[Bb*Hh*Tt*Cc];
__device__ __align__(16) float g_ao[Bb*Tt*Ee];

// ---------------- packed f32x2 helpers ---------------------------------------
__device__ __forceinline__ unsigned long long dup2(float x) {
    unsigned long long r;
    asm("mov.b64 %0, {%1, %1};" : "=l"(r) : "f"(x));
    return r;
}
__device__ __forceinline__ void fma2(unsigned long long& d,
                                     unsigned long long a, unsigned long long b) {
    asm("fma.rn.f32x2 %0, %1, %2, %0;" : "+l"(d) : "l"(a), "l"(b));
}

// ---------------- 128x128 fp32 GEMM tile body (R9: reg dbl-buffer, FMA2) -----
__device__ __forceinline__ void gemm128_body(
        const float* __restrict__ A, const float* __restrict__ B,
        float* __restrict__ Cmat, int N, int K, int m0, int n0,
        float (*As)[8][128], float (*Bs)[8][128]) {
    int tid = threadIdx.x;
    int tx = tid & 15, ty = tid >> 4;
    int arow = tid >> 1, akq = (tid & 1) * 4;
    int brow = tid >> 5, bnq = (tid & 31) * 4;

    const float* Aptr = A + (size_t)(m0 + arow) * K + akq;
    const float* Bptr = B + (size_t)brow * N + n0 + bnq;

    unsigned long long acc2[8][4];
#pragma unroll
    for (int i = 0; i < 8; i++)
#pragma unroll
        for (int j = 0; j < 4; j++) acc2[i][j] = 0ull;

    float4 av = *(const float4*)Aptr;
    float4 bv = *(const float4*)Bptr;
    As[0][akq + 0][arow] = av.x;
    As[0][akq + 1][arow] = av.y;
    As[0][akq + 2][arow] = av.z;
    As[0][akq + 3][arow] = av.w;
    *(float4*)&Bs[0][brow][bnq] = bv;
    __syncthreads();

    int NT = K >> 3;
    int cur = 0;
    for (int kt = 0; kt < NT; kt++) {
        if (kt + 1 < NT) {
            av = *(const float4*)(Aptr + (kt + 1) * 8);
            bv = *(const float4*)(Bptr + (size_t)(kt + 1) * 8 * N);
        }
#pragma unroll
        for (int k = 0; k < 8; k++) {
            float4 a0 = *(const float4*)&As[cur][k][ty * 8];
            float4 a1 = *(const float4*)&As[cur][k][ty * 8 + 4];
            ulonglong2 bl0 = *(const ulonglong2*)&Bs[cur][k][tx * 8];
            ulonglong2 bl1 = *(const ulonglong2*)&Bs[cur][k][tx * 8 + 4];
            float ra[8] = {a0.x, a0.y, a0.z, a0.w, a1.x, a1.y, a1.z, a1.w};
            unsigned long long rb2[4] = {bl0.x, bl0.y, bl1.x, bl1.y};
#pragma unroll
            for (int i = 0; i < 8; i++) {
                unsigned long long a2 = dup2(ra[i]);
#pragma unroll
                for (int j = 0; j < 4; j++) fma2(acc2[i][j], a2, rb2[j]);
            }
        }
        if (kt + 1 < NT) {
            int nxt = cur ^ 1;
            As[nxt][akq + 0][arow] = av.x;
            As[nxt][akq + 1][arow] = av.y;
            As[nxt][akq + 2][arow] = av.z;
            As[nxt][akq + 3][arow] = av.w;
            *(float4*)&Bs[nxt][brow][bnq] = bv;
            __syncthreads();
            cur = nxt;
        }
    }

#pragma unroll
    for (int i = 0; i < 8; i++) {
        float* crow = Cmat + (size_t)(m0 + ty * 8 + i) * N + n0 + tx * 8;
        *(ulonglong2*)crow       = make_ulonglong2(acc2[i][0], acc2[i][1]);
        *(ulonglong2*)(crow + 4) = make_ulonglong2(acc2[i][2], acc2[i][3]);
    }
}

// ---------------- skinny row GEMM: C[m, n0:+128], intra-block split-K --------
__device__ __forceinline__ void skinny_body(
        const float* __restrict__ A, const float* __restrict__ B,
        float* __restrict__ C, int N, int K, int m, int n0) {
    __shared__ float red[128];
    int t = threadIdx.x;
    int n = n0 + (t & 127);
    int kc = t >> 7;
    int kh = K >> 1;
    const float* a = A + (size_t)m * K + kc * kh;
    const float* b = B + (size_t)(kc * kh) * N + n;
    float acc = 0.f;
#pragma unroll 8
    for (int k = 0; k < kh; k++) acc += a[k] * b[(size_t)k * N];
    if (kc) red[t & 127] = acc;
    __syncthreads();
    if (!kc) C[(size_t)m * N + n] = acc + red[t & 127];
}

// ---------------- one launch for ALL projections ------------------------------
__global__ __launch_bounds__(256) void mega_gemm(
        const float* __restrict__ hs, const float* __restrict__ Wq,
        const float* __restrict__ Wkv,
        const float* __restrict__ pe, const float* __restrict__ Wpos,
        const float* __restrict__ ce, const float* __restrict__ Wchan,
        float* __restrict__ q, float* __restrict__ kv,
        float* __restrict__ tk, float* __restrict__ ck) {
    __shared__ float As[2][8][128];
    __shared__ float Bs[2][8][128];
    int blk = blockIdx.x;
    if (blk < 128) {
        gemm128_body(hs, Wq, q, Ee, Ee, (blk >> 3) * 128, (blk & 7) * 128, As, Bs);
    } else if (blk < 192) {
        int b = blk - 128;
        gemm128_body(hs, Wkv, kv, 2 * EKVv, Ee, (b >> 2) * 128, (b & 3) * 128, As, Bs);
    } else if (blk < 448) {
        int b = blk - 192;
        skinny_body(pe, Wpos, tk, EKVv, Ee, b >> 1, (b & 1) * 128);
    } else {
        int b = blk - 448;
        skinny_body(ce, Wchan, ck, EKVv, Ee, b >> 1, (b & 1) * 128);
    }
}

// ---------------- standalone GEMM for the output projection ------------------
__global__ __launch_bounds__(256) void sgemm128(
        const float* __restrict__ A, const float* __restrict__ B,
        float* __restrict__ Cmat, int N, int K) {
    __shared__ float As[2][8][128];
    __shared__ float Bs[2][8][128];
    gemm128_body(A, B, Cmat, N, K, blockIdx.y * 128, blockIdx.x * 128, As, Bs);
}

// ---------------- merged time_att + chan_att ---------------------------------
__global__ __launch_bounds__(256) void rel_att_kernel(
        const float* __restrict__ q, const float* __restrict__ bias) {
    __shared__ float qs[32][65];
    __shared__ float ks[128][64];
    int blk = blockIdx.x;
    int tid = threadIdx.x;
    if (blk < 1024) {
        int bh = blk & 31;
        int b = bh / Hh, h = bh % Hh, kvh = h / Gg;
        int t0 = (blk >> 5) * 32;
        for (int i = tid; i < 32 * 64; i += 256) {
            int r = i >> 6, d = i & 63;
            qs[r][d] = q[((size_t)(b * Tt + t0 + r)) * Ee + h * Dd + d]
                     + bias[EKVv + kvh * Dd + d];
        }
        for (int i = tid; i < 128 * 64; i += 256) {
            int p = i >> 6, d = i & 63;
            ks[p][d] = g_tk[p * EKVv + kvh * Dd + d];
        }
        __syncthreads();
        int r = tid & 31;
        int pb = (tid >> 5) * 16;
        float acc[16];
#pragma unroll
        for (int j = 0; j < 16; j++) acc[j] = 0.f;
        for (int d = 0; d < 64; d++) {
            float qv = qs[r][d];
#pragma unroll
            for (int j = 0; j < 16; j++) acc[j] += qv * ks[pb + j][d];
        }
        float* dst = g_time + ((size_t)bh * Tt + t0 + r) * Pp + pb;
#pragma unroll
        for (int j = 0; j < 16; j++) dst[j] = acc[j];
    } else {
        int bc = blk - 1024;
        int bh = bc & 31;
        int b = bh / Hh, h = bh % Hh, kvh = h / Gg;
        int t0 = (bc >> 5) * 32;
        for (int i = tid; i < 32 * 64; i += 256) {
            int r = i >> 6, d = i & 63;
            qs[r][d] = q[((size_t)(b * Tt + t0 + r)) * Ee + h * Dd + d]
                     + bias[2 * EKVv + kvh * Dd + d];
        }
        for (int i = tid; i < 8 * 64; i += 256) {
            int c = i >> 6, d = i & 63;
            ks[c][d] = g_ck[c * EKVv + kvh * Dd + d];
        }
        __syncthreads();
        int r = tid >> 3, c = tid & 7;
        float acc = 0.f;
#pragma unroll
        for (int d = 0; d < 64; d++) acc += qs[r][d] * ks[c][d];
        g_chan[((size_t)bh * Tt + t0 + r) * Cc + c] = acc;
    }
}

// ---------------- attention core: one block per (b, h, pt) -------------------
// smem: qg[8][68] + lg[8][1025] + rinv + union{ gks[128][68] | sred[8][8][64] }
__global__ __launch_bounds__(256) void attn_kernel(
        const float* __restrict__ q, const float* __restrict__ bias) {
    __shared__ float qg[8][68];
    __shared__ float lg[8][1025];
    __shared__ float rinv[8];
    __shared__ __align__(16) float upool[128 * 68];   // gks / sred union
    float (*gks)[68] = (float(*)[68])upool;           // [128][68]
    float (*sred)[8][64] = (float(*)[8][64])upool;    // [8][8][64]

    int blk = blockIdx.x;
    int pt = (Pp - 1) - (blk % Pp);              // big-S blocks first
    int h  = (blk / Pp) % Hh;
    int b  = blk / (Pp * Hh);
    int kvh = h / Gg;
    int tid = threadIdx.x;
    int t0 = pt * Cc;

    for (int i = tid; i < 8 * 64; i += 256) {
        int c = i >> 6, d = i & 63;
        qg[c][d] = q[((size_t)(b * Tt + t0 + c)) * Ee + h * Dd + d]
                 + bias[kvh * Dd + d];
    }
    __syncthreads();

    int S = (pt + 1) * Cc;
    const float* tbase = g_time + (size_t)(b * Hh + h) * Tt * Pp;
    const float* cbase = g_chan + (size_t)(b * Hh + h) * Tt * Cc;

    // base logits, s-fastest mapping: lane-consecutive s0 -> coalesced tbase
    for (int s0 = tid; s0 < S; s0 += 256) {
        int ps = s0 >> 3, cs = s0 & 7;
#pragma unroll
        for (int c = 0; c < 8; c++) {
            int t = t0 + c;
            unsigned m = (unsigned)(t + 1) * Pp + ps;
            unsigned i2 = m / (Tt + 1);
            float tv = 0.f;
            if (m - i2 * (Tt + 1) != 0) tv = tbase[m - i2 - 1];
            int dc = c - cs; dc = dc < 0 ? -dc : dc;
            float cv = cbase[t * Cc + (Cc - 1 - dc)];
            lg[c][s0] = tv + cv;
        }
    }
    __syncthreads();

    // global band: stage gk rows through smem in 128-row tiles (each row
    // fetched ONCE from L2, reused by all 8 channel rows)
    int gLow = (pt == Pp - 1) ? 0 : ((pt > 10 ? pt - 10 : 0) * Cc);
    for (int sb = gLow; sb < S; sb += 128) {
        int rows = min(128, S - sb);
        for (int i = tid; i < rows * 16; i += 256) {
            int r = i >> 4, u = i & 15;
            const float4* src = (const float4*)(g_kv
                + ((size_t)(b * Tt + sb + r)) * (2 * EKVv) + kvh * Dd);
            *(float4*)&gks[r][u * 4] = src[u];
        }
        __syncthreads();
        for (int idx = tid; idx < rows * 8; idx += 256) {
            int r = idx >> 3, c = idx & 7;
            float acc = 0.f;
#pragma unroll
            for (int d4 = 0; d4 < 16; d4++) {
                float4 gv = *(const float4*)&gks[r][d4 * 4];
                float4 qv = *(const float4*)&qg[c][d4 * 4];
                acc += qv.x * gv.x + qv.y * gv.y + qv.z * gv.z + qv.w * gv.w;
            }
            lg[c][sb + r] += acc;
        }
        __syncthreads();
    }

    // softmax: warp w owns row w
    int w = tid >> 5, lane = tid & 31;
    {
        float mx = -1e30f;
        for (int s = lane; s < S; s += 32) mx = fmaxf(mx, lg[w][s] * 0.125f);
#pragma unroll
        for (int o = 16; o > 0; o >>= 1)
            mx = fmaxf(mx, __shfl_xor_sync(0xffffffffu, mx, o));
        float sum = 0.f;
        for (int s = lane; s < S; s += 32) {
            float e = __expf(lg[w][s] * 0.125f - mx);
            lg[w][s] = e;
            sum += e;
        }
#pragma unroll
        for (int o = 16; o > 0; o >>= 1)
            sum += __shfl_xor_sync(0xffffffffu, sum, o);
        if (lane == 0) rinv[w] = 1.f / sum;
    }
    __syncthreads();

    // out[c,d] = sum_s w[c,s]*v[s,d]; v loaded once per (s, d-pair)
    {
        int dp = (tid & 31) * 2;
        int sg = tid >> 5;
        const float* vbase = g_kv + (size_t)b * Tt * (2 * EKVv) + EKVv
                           + kvh * Dd + dp;
        float accx[8], accy[8];
#pragma unroll
        for (int c = 0; c < 8; c++) { accx[c] = 0.f; accy[c] = 0.f; }
        for (int s = sg; s < S; s += 8) {
            float2 vv = *(const float2*)(vbase + (size_t)s * (2 * EKVv));
#pragma unroll
            for (int c = 0; c < 8; c++) {
                float wgt = lg[c][s];
                accx[c] += wgt * vv.x;
                accy[c] += wgt * vv.y;
            }
        }
#pragma unroll
        for (int c = 0; c < 8; c++) {
            sred[sg][c][dp]     = accx[c];
            sred[sg][c][dp + 1] = accy[c];
        }
    }
    __syncthreads();
    for (int i = tid; i < 512; i += 256) {
        int c = i >> 6, dd = i & 63;
        float o = ((sred[0][c][dd] + sred[1][c][dd])
                 + (sred[2][c][dd] + sred[3][c][dd]))
                + ((sred[4][c][dd] + sred[5][c][dd])
                 + (sred[6][c][dd] + sred[7][c][dd]));
        g_ao[((size_t)(b * Tt + t0 + c)) * Ee + h * Dd + dd] = o * rinv[c];
    }
}

// ---------------- launch ----------------------------------------------------
extern "C" void kernel_launch(void* const* d_in, const int* in_sizes, int n_in,
                              void* d_out, int out_size) {
    const float* hs    = (const float*)d_in[0];
    const float* pe    = (const float*)d_in[1];
    const float* ce    = (const float*)d_in[2];
    const float* Wq    = (const float*)d_in[3];
    const float* Wkv   = (const float*)d_in[4];
    const float* Wpos  = (const float*)d_in[5];
    const float* Wchan = (const float*)d_in[6];
    const float* Wproj = (const float*)d_in[7];
    const float* bias  = (const float*)d_in[8];

    float *q, *kv, *tk, *ck, *ao;
    cudaGetSymbolAddress((void**)&q,  g_q);
    cudaGetSymbolAddress((void**)&kv, g_kv);
    cudaGetSymbolAddress((void**)&tk, g_tk);
    cudaGetSymbolAddress((void**)&ck, g_ck);
    cudaGetSymbolAddress((void**)&ao, g_ao);

    // all projections in one chip-filling launch
    mega_gemm<<<464, 256>>>(hs, Wq, Wkv, pe, Wpos, ce, Wchan, q, kv, tk, ck);

    // relative logits (time + chan merged)
    rel_att_kernel<<<2048, 256>>>(q, bias);

    // attention core
    attn_kernel<<<Bb * Hh * Pp, 256>>>(q, bias);

    // output projection -> d_out
    sgemm128<<<dim3(Ee / 128, (Bb * Tt) / 128), 256>>>(ao, Wproj, (float*)d_out, Ee, Ee);
}

// round 13
// speedup vs baseline: 1.0828x; 1.0006x over previous
#include <cuda_runtime.h>

#define Bb  2
#define Pp  128
#define Cc  8
#define Hh  16
#define Gg  4
#define Dd  64
#define Ee  1024
#define EKVv 256
#define Tt  1024

// ---------------- scratch (device globals; no allocation allowed) -----------
__device__ __align__(16) float g_q[Bb*Tt*Ee];
__device__ __align__(16) float g_kv[Bb*Tt*2*EKVv];
__device__ __align__(16) float g_tk[Pp*EKVv];
__device__ __align__(16) float g_ck[Cc*EKVv];
__device__ __align__(16) float g_time[Bb*Hh*Tt*Pp];
__device__ __align__(16) float g_chan[Bb*Hh*Tt*Cc];
__device__ __align__(16) float g_ao[Bb*Tt*Ee];

// ---------------- packed f32x2 helpers ---------------------------------------
__device__ __forceinline__ unsigned long long dup2(float x) {
    unsigned long long r;
    asm("mov.b64 %0, {%1, %1};" : "=l"(r) : "f"(x));
    return r;
}
__device__ __forceinline__ void fma2(unsigned long long& d,
                                     unsigned long long a, unsigned long long b) {
    asm("fma.rn.f32x2 %0, %1, %2, %0;" : "+l"(d) : "l"(a), "l"(b));
}

// ---------------- 128x128 fp32 GEMM tile body (R9: reg dbl-buffer, FMA2) -----
__device__ __forceinline__ void gemm128_body(
        const float* __restrict__ A, const float* __restrict__ B,
        float* __restrict__ Cmat, int N, int K, int m0, int n0,
        float (*As)[8][128], float (*Bs)[8][128]) {
    int tid = threadIdx.x;
    int tx = tid & 15, ty = tid >> 4;
    int arow = tid >> 1, akq = (tid & 1) * 4;
    int brow = tid >> 5, bnq = (tid & 31) * 4;

    const float* Aptr = A + (size_t)(m0 + arow) * K + akq;
    const float* Bptr = B + (size_t)brow * N + n0 + bnq;

    unsigned long long acc2[8][4];
#pragma unroll
    for (int i = 0; i < 8; i++)
#pragma unroll
        for (int j = 0; j < 4; j++) acc2[i][j] = 0ull;

    float4 av = *(const float4*)Aptr;
    float4 bv = *(const float4*)Bptr;
    As[0][akq + 0][arow] = av.x;
    As[0][akq + 1][arow] = av.y;
    As[0][akq + 2][arow] = av.z;
    As[0][akq + 3][arow] = av.w;
    *(float4*)&Bs[0][brow][bnq] = bv;
    __syncthreads();

    int NT = K >> 3;
    int cur = 0;
    for (int kt = 0; kt < NT; kt++) {
        if (kt + 1 < NT) {
            av = *(const float4*)(Aptr + (kt + 1) * 8);
            bv = *(const float4*)(Bptr + (size_t)(kt + 1) * 8 * N);
        }
#pragma unroll
        for (int k = 0; k < 8; k++) {
            float4 a0 = *(const float4*)&As[cur][k][ty * 8];
            float4 a1 = *(const float4*)&As[cur][k][ty * 8 + 4];
            ulonglong2 bl0 = *(const ulonglong2*)&Bs[cur][k][tx * 8];
            ulonglong2 bl1 = *(const ulonglong2*)&Bs[cur][k][tx * 8 + 4];
            float ra[8] = {a0.x, a0.y, a0.z, a0.w, a1.x, a1.y, a1.z, a1.w};
            unsigned long long rb2[4] = {bl0.x, bl0.y, bl1.x, bl1.y};
#pragma unroll
            for (int i = 0; i < 8; i++) {
                unsigned long long a2 = dup2(ra[i]);
#pragma unroll
                for (int j = 0; j < 4; j++) fma2(acc2[i][j], a2, rb2[j]);
            }
        }
        if (kt + 1 < NT) {
            int nxt = cur ^ 1;
            As[nxt][akq + 0][arow] = av.x;
            As[nxt][akq + 1][arow] = av.y;
            As[nxt][akq + 2][arow] = av.z;
            As[nxt][akq + 3][arow] = av.w;
            *(float4*)&Bs[nxt][brow][bnq] = bv;
            __syncthreads();
            cur = nxt;
        }
    }

#pragma unroll
    for (int i = 0; i < 8; i++) {
        float* crow = Cmat + (size_t)(m0 + ty * 8 + i) * N + n0 + tx * 8;
        *(ulonglong2*)crow       = make_ulonglong2(acc2[i][0], acc2[i][1]);
        *(ulonglong2*)(crow + 4) = make_ulonglong2(acc2[i][2], acc2[i][3]);
    }
}

// ---------------- skinny row GEMM: C[m, n0:+128], intra-block split-K --------
__device__ __forceinline__ void skinny_body(
        const float* __restrict__ A, const float* __restrict__ B,
        float* __restrict__ C, int N, int K, int m, int n0) {
    __shared__ float red[128];
    int t = threadIdx.x;
    int n = n0 + (t & 127);
    int kc = t >> 7;
    int kh = K >> 1;
    const float* a = A + (size_t)m * K + kc * kh;
    const float* b = B + (size_t)(kc * kh) * N + n;
    float acc = 0.f;
#pragma unroll 8
    for (int k = 0; k < kh; k++) acc += a[k] * b[(size_t)k * N];
    if (kc) red[t & 127] = acc;
    __syncthreads();
    if (!kc) C[(size_t)m * N + n] = acc + red[t & 127];
}

// ---------------- one launch for ALL projections ------------------------------
__global__ __launch_bounds__(256) void mega_gemm(
        const float* __restrict__ hs, const float* __restrict__ Wq,
        const float* __restrict__ Wkv,
        const float* __restrict__ pe, const float* __restrict__ Wpos,
        const float* __restrict__ ce, const float* __restrict__ Wchan,
        float* __restrict__ q, float* __restrict__ kv,
        float* __restrict__ tk, float* __restrict__ ck) {
    __shared__ float As[2][8][128];
    __shared__ float Bs[2][8][128];
    int blk = blockIdx.x;
    if (blk < 128) {
        gemm128_body(hs, Wq, q, Ee, Ee, (blk >> 3) * 128, (blk & 7) * 128, As, Bs);
    } else if (blk < 192) {
        int b = blk - 128;
        gemm128_body(hs, Wkv, kv, 2 * EKVv, Ee, (b >> 2) * 128, (b & 3) * 128, As, Bs);
    } else if (blk < 448) {
        int b = blk - 192;
        skinny_body(pe, Wpos, tk, EKVv, Ee, b >> 1, (b & 1) * 128);
    } else {
        int b = blk - 448;
        skinny_body(ce, Wchan, ck, EKVv, Ee, b >> 1, (b & 1) * 128);
    }
}

// ---------------- standalone GEMM for the output projection ------------------
__global__ __launch_bounds__(256) void sgemm128(
        const float* __restrict__ A, const float* __restrict__ B,
        float* __restrict__ Cmat, int N, int K) {
    __shared__ float As[2][8][128];
    __shared__ float Bs[2][8][128];
    gemm128_body(A, B, Cmat, N, K, blockIdx.y * 128, blockIdx.x * 128, As, Bs);
}

// ---------------- merged time_att + chan_att ---------------------------------
__global__ __launch_bounds__(256) void rel_att_kernel(
        const float* __restrict__ q, const float* __restrict__ bias) {
    __shared__ float qs[32][65];
    __shared__ float ks[128][64];
    int blk = blockIdx.x;
    int tid = threadIdx.x;
    if (blk < 1024) {
        int bh = blk & 31;
        int b = bh / Hh, h = bh % Hh, kvh = h / Gg;
        int t0 = (blk >> 5) * 32;
        for (int i = tid; i < 32 * 64; i += 256) {
            int r = i >> 6, d = i & 63;
            qs[r][d] = q[((size_t)(b * Tt + t0 + r)) * Ee + h * Dd + d]
                     + bias[EKVv + kvh * Dd + d];
        }
        for (int i = tid; i < 128 * 64; i += 256) {
            int p = i >> 6, d = i & 63;
            ks[p][d] = g_tk[p * EKVv + kvh * Dd + d];
        }
        __syncthreads();
        int r = tid & 31;
        int pb = (tid >> 5) * 16;
        float acc[16];
#pragma unroll
        for (int j = 0; j < 16; j++) acc[j] = 0.f;
        for (int d = 0; d < 64; d++) {
            float qv = qs[r][d];
#pragma unroll
            for (int j = 0; j < 16; j++) acc[j] += qv * ks[pb + j][d];
        }
        float* dst = g_time + ((size_t)bh * Tt + t0 + r) * Pp + pb;
#pragma unroll
        for (int j = 0; j < 16; j++) dst[j] = acc[j];
    } else {
        int bc = blk - 1024;
        int bh = bc & 31;
        int b = bh / Hh, h = bh % Hh, kvh = h / Gg;
        int t0 = (bc >> 5) * 32;
        for (int i = tid; i < 32 * 64; i += 256) {
            int r = i >> 6, d = i & 63;
            qs[r][d] = q[((size_t)(b * Tt + t0 + r)) * Ee + h * Dd + d]
                     + bias[2 * EKVv + kvh * Dd + d];
        }
        for (int i = tid; i < 8 * 64; i += 256) {
            int c = i >> 6, d = i & 63;
            ks[c][d] = g_ck[c * EKVv + kvh * Dd + d];
        }
        __syncthreads();
        int r = tid >> 3, c = tid & 7;
        float acc = 0.f;
#pragma unroll
        for (int d = 0; d < 64; d++) acc += qs[r][d] * ks[c][d];
        g_chan[((size_t)bh * Tt + t0 + r) * Cc + c] = acc;
    }
}

// ---------------- attention core: one block per (b, h, pt) -------------------
// smem: qg[8][68] + lg[8][1025] + rinv + union{ gks[128][68] | sred[8][8][64] }
__global__ __launch_bounds__(256) void attn_kernel(
        const float* __restrict__ q, const float* __restrict__ bias) {
    __shared__ float qg[8][68];
    __shared__ float lg[8][1025];
    __shared__ float rinv[8];
    __shared__ __align__(16) float upool[128 * 68];   // gks / sred union
    float (*gks)[68] = (float(*)[68])upool;           // [128][68]
    float (*sred)[8][64] = (float(*)[8][64])upool;    // [8][8][64]

    int blk = blockIdx.x;
    int pt = (Pp - 1) - (blk % Pp);              // big-S blocks first
    int h  = (blk / Pp) % Hh;
    int b  = blk / (Pp * Hh);
    int kvh = h / Gg;
    int tid = threadIdx.x;
    int t0 = pt * Cc;

    for (int i = tid; i < 8 * 64; i += 256) {
        int c = i >> 6, d = i & 63;
        qg[c][d] = q[((size_t)(b * Tt + t0 + c)) * Ee + h * Dd + d]
                 + bias[kvh * Dd + d];
    }
    __syncthreads();

    int S = (pt + 1) * Cc;
    const float* tbase = g_time + (size_t)(b * Hh + h) * Tt * Pp;
    const float* cbase = g_chan + (size_t)(b * Hh + h) * Tt * Cc;

    // base logits, s-fastest mapping: lane-consecutive s0 -> coalesced tbase
    for (int s0 = tid; s0 < S; s0 += 256) {
        int ps = s0 >> 3, cs = s0 & 7;
#pragma unroll
        for (int c = 0; c < 8; c++) {
            int t = t0 + c;
            unsigned m = (unsigned)(t + 1) * Pp + ps;
            unsigned i2 = m / (Tt + 1);
            float tv = 0.f;
            if (m - i2 * (Tt + 1) != 0) tv = tbase[m - i2 - 1];
            int dc = c - cs; dc = dc < 0 ? -dc : dc;
            float cv = cbase[t * Cc + (Cc - 1 - dc)];
            lg[c][s0] = tv + cv;
        }
    }
    __syncthreads();

    // global band: stage gk rows through smem in 128-row tiles (each row
    // fetched ONCE from L2, reused by all 8 channel rows)
    int gLow = (pt == Pp - 1) ? 0 : ((pt > 10 ? pt - 10 : 0) * Cc);
    for (int sb = gLow; sb < S; sb += 128) {
        int rows = min(128, S - sb);
        for (int i = tid; i < rows * 16; i += 256) {
            int r = i >> 4, u = i & 15;
            const float4* src = (const float4*)(g_kv
                + ((size_t)(b * Tt + sb + r)) * (2 * EKVv) + kvh * Dd);
            *(float4*)&gks[r][u * 4] = src[u];
        }
        __syncthreads();
        for (int idx = tid; idx < rows * 8; idx += 256) {
            int r = idx >> 3, c = idx & 7;
            float acc = 0.f;
#pragma unroll
            for (int d4 = 0; d4 < 16; d4++) {
                float4 gv = *(const float4*)&gks[r][d4 * 4];
                float4 qv = *(const float4*)&qg[c][d4 * 4];
                acc += qv.x * gv.x + qv.y * gv.y + qv.z * gv.z + qv.w * gv.w;
            }
            lg[c][sb + r] += acc;
        }
        __syncthreads();
    }

    // softmax: warp w owns row w
    int w = tid >> 5, lane = tid & 31;
    {
        float mx = -1e30f;
        for (int s = lane; s < S; s += 32) mx = fmaxf(mx, lg[w][s] * 0.125f);
#pragma unroll
        for (int o = 16; o > 0; o >>= 1)
            mx = fmaxf(mx, __shfl_xor_sync(0xffffffffu, mx, o));
        float sum = 0.f;
        for (int s = lane; s < S; s += 32) {
            float e = __expf(lg[w][s] * 0.125f - mx);
            lg[w][s] = e;
            sum += e;
        }
#pragma unroll
        for (int o = 16; o > 0; o >>= 1)
            sum += __shfl_xor_sync(0xffffffffu, sum, o);
        if (lane == 0) rinv[w] = 1.f / sum;
    }
    __syncthreads();

    // out[c,d] = sum_s w[c,s]*v[s,d]; v loaded once per (s, d-pair)
    {
        int dp = (tid & 31) * 2;
        int sg = tid >> 5;
        const float* vbase = g_kv + (size_t)b * Tt * (2 * EKVv) + EKVv
                           + kvh * Dd + dp;
        float accx[8], accy[8];
#pragma unroll
        for (int c = 0; c < 8; c++) { accx[c] = 0.f; accy[c] = 0.f; }
        for (int s = sg; s < S; s += 8) {
            float2 vv = *(const float2*)(vbase + (size_t)s * (2 * EKVv));
#pragma unroll
            for (int c = 0; c < 8; c++) {
                float wgt = lg[c][s];
                accx[c] += wgt * vv.x;
                accy[c] += wgt * vv.y;
            }
        }
#pragma unroll
        for (int c = 0; c < 8; c++) {
            sred[sg][c][dp]     = accx[c];
            sred[sg][c][dp + 1] = accy[c];
        }
    }
    __syncthreads();
    for (int i = tid; i < 512; i += 256) {
        int c = i >> 6, dd = i & 63;
        float o = ((sred[0][c][dd] + sred[1][c][dd])
                 + (sred[2][c][dd] + sred[3][c][dd]))
                + ((sred[4][c][dd] + sred[5][c][dd])
                 + (sred[6][c][dd] + sred[7][c][dd]));
        g_ao[((size_t)(b * Tt + t0 + c)) * Ee + h * Dd + dd] = o * rinv[c];
    }
}

// ---------------- launch ----------------------------------------------------
extern "C" void kernel_launch(void* const* d_in, const int* in_sizes, int n_in,
                              void* d_out, int out_size) {
    const float* hs    = (const float*)d_in[0];
    const float* pe    = (const float*)d_in[1];
    const float* ce    = (const float*)d_in[2];
    const float* Wq    = (const float*)d_in[3];
    const float* Wkv   = (const float*)d_in[4];
    const float* Wpos  = (const float*)d_in[5];
    const float* Wchan = (const float*)d_in[6];
    const float* Wproj = (const float*)d_in[7];
    const float* bias  = (const float*)d_in[8];

    float *q, *kv, *tk, *ck, *ao;
    cudaGetSymbolAddress((void**)&q,  g_q);
    cudaGetSymbolAddress((void**)&kv, g_kv);
    cudaGetSymbolAddress((void**)&tk, g_tk);
    cudaGetSymbolAddress((void**)&ck, g_ck);
    cudaGetSymbolAddress((void**)&ao, g_ao);

    // all projections in one chip-filling launch
    mega_gemm<<<464, 256>>>(hs, Wq, Wkv, pe, Wpos, ce, Wchan, q, kv, tk, ck);

    // relative logits (time + chan merged)
    rel_att_kernel<<<2048, 256>>>(q, bias);

    // attention core
    attn_kernel<<<Bb * Hh * Pp, 256>>>(q, bias);

    // output projection -> d_out
    sgemm128<<<dim3(Ee / 128, (Bb * Tt) / 128), 256>>>(ao, Wproj, (float*)d_out, Ee, Ee);
}

// round 14
// speedup vs baseline: 1.1953x; 1.1039x over previous
#include <cuda_runtime.h>

#define Bb  2
#define Pp  128
#define Cc  8
#define Hh  16
#define Gg  4
#define Dd  64
#define Ee  1024
#define EKVv 256
#define Tt  1024

// ---------------- scratch (device globals; no allocation allowed) -----------
__device__ __align__(16) float g_q[Bb*Tt*Ee];
__device__ __align__(16) float g_kv[Bb*Tt*2*EKVv];
__device__ __align__(16) float g_tk[Pp*EKVv];
__device__ __align__(16) float g_ck[Cc*EKVv];
__device__ __align__(16) float g_time[Bb*Hh*Tt*Pp];
__device__ __align__(16) float g_chan[Bb*Hh*Tt*Cc];
__device__ __align__(16) float g_ao[Bb*Tt*Ee];

// ---------------- packed f32x2 helpers ---------------------------------------
__device__ __forceinline__ unsigned long long dup2(float x) {
    unsigned long long r;
    asm("mov.b64 %0, {%1, %1};" : "=l"(r) : "f"(x));
    return r;
}
__device__ __forceinline__ void fma2(unsigned long long& d,
                                     unsigned long long a, unsigned long long b) {
    asm("fma.rn.f32x2 %0, %1, %2, %0;" : "+l"(d) : "l"(a), "l"(b));
}
__device__ __forceinline__ void unpack2(unsigned long long v, float& lo, float& hi) {
    asm("mov.b64 {%0, %1}, %2;" : "=f"(lo), "=f"(hi) : "l"(v));
}

// ---------------- 64x128 fp32 GEMM tile body (8x8/thread, 128 thr, FMA2) ----
// C[m0:+64, n0:+128] = A(MxK) @ B(KxN). K%8==0, rows 16B-aligned.
__device__ __forceinline__ void gemm64x128_body(
        const float* __restrict__ A, const float* __restrict__ B,
        float* __restrict__ Cmat, int N, int K, int m0, int n0,
        float (*As)[8][64], float (*Bs)[8][128]) {
    int tid = threadIdx.x;
    int tx = tid & 15, ty = tid >> 4;           // 16 n-groups x 8 m-groups
    int arow = tid >> 1, akq = (tid & 1) * 4;   // 64 rows x 2 quads
    int brow = tid >> 4, bnq = (tid & 15) * 8;  // 8 k-rows x 16 oct

    const float* Aptr = A + (size_t)(m0 + arow) * K + akq;
    const float* Bptr = B + (size_t)brow * N + n0 + bnq;

    unsigned long long acc2[8][4];
#pragma unroll
    for (int i = 0; i < 8; i++)
#pragma unroll
        for (int j = 0; j < 4; j++) acc2[i][j] = 0ull;

    float4 av = *(const float4*)Aptr;
    float4 bv0 = *(const float4*)Bptr;
    float4 bv1 = *(const float4*)(Bptr + 4);
    As[0][akq + 0][arow] = av.x;
    As[0][akq + 1][arow] = av.y;
    As[0][akq + 2][arow] = av.z;
    As[0][akq + 3][arow] = av.w;
    *(float4*)&Bs[0][brow][bnq]     = bv0;
    *(float4*)&Bs[0][brow][bnq + 4] = bv1;
    __syncthreads();

    int NT = K >> 3;
    int cur = 0;
    for (int kt = 0; kt < NT; kt++) {
        if (kt + 1 < NT) {
            av  = *(const float4*)(Aptr + (kt + 1) * 8);
            bv0 = *(const float4*)(Bptr + (size_t)(kt + 1) * 8 * N);
            bv1 = *(const float4*)(Bptr + (size_t)(kt + 1) * 8 * N + 4);
        }
#pragma unroll
        for (int k = 0; k < 8; k++) {
            float4 a0 = *(const float4*)&As[cur][k][ty * 8];
            float4 a1 = *(const float4*)&As[cur][k][ty * 8 + 4];
            ulonglong2 bl0 = *(const ulonglong2*)&Bs[cur][k][tx * 8];
            ulonglong2 bl1 = *(const ulonglong2*)&Bs[cur][k][tx * 8 + 4];
            float ra[8] = {a0.x, a0.y, a0.z, a0.w, a1.x, a1.y, a1.z, a1.w};
            unsigned long long rb2[4] = {bl0.x, bl0.y, bl1.x, bl1.y};
#pragma unroll
            for (int i = 0; i < 8; i++) {
                unsigned long long a2 = dup2(ra[i]);
#pragma unroll
                for (int j = 0; j < 4; j++) fma2(acc2[i][j], a2, rb2[j]);
            }
        }
        if (kt + 1 < NT) {
            int nxt = cur ^ 1;
            As[nxt][akq + 0][arow] = av.x;
            As[nxt][akq + 1][arow] = av.y;
            As[nxt][akq + 2][arow] = av.z;
            As[nxt][akq + 3][arow] = av.w;
            *(float4*)&Bs[nxt][brow][bnq]     = bv0;
            *(float4*)&Bs[nxt][brow][bnq + 4] = bv1;
            __syncthreads();
            cur = nxt;
        }
    }

#pragma unroll
    for (int i = 0; i < 8; i++) {
        float* crow = Cmat + (size_t)(m0 + ty * 8 + i) * N + n0 + tx * 8;
        *(ulonglong2*)crow       = make_ulonglong2(acc2[i][0], acc2[i][1]);
        *(ulonglong2*)(crow + 4) = make_ulonglong2(acc2[i][2], acc2[i][3]);
    }
}

// ---------------- skinny row GEMM: C[m, n0:+128], split-K (128 thr) ----------
__device__ __forceinline__ void skinny_body(
        const float* __restrict__ A, const float* __restrict__ B,
        float* __restrict__ C, int N, int K, int m, int n0) {
    int t = threadIdx.x;
    int n = n0 + t;
    const float* a = A + (size_t)m * K;
    const float* b = B + n;
    float acc = 0.f;
#pragma unroll 8
    for (int k = 0; k < K; k++) acc += a[k] * b[(size_t)k * N];
    C[(size_t)m * N + n] = acc;
}

// ---------------- one launch for ALL projections ------------------------------
// blocks: [0,256) q | [256,384) kv | [384,640) tk | [640,656) ck
__global__ __launch_bounds__(128) void mega_gemm(
        const float* __restrict__ hs, const float* __restrict__ Wq,
        const float* __restrict__ Wkv,
        const float* __restrict__ pe, const float* __restrict__ Wpos,
        const float* __restrict__ ce, const float* __restrict__ Wchan,
        float* __restrict__ q, float* __restrict__ kv,
        float* __restrict__ tk, float* __restrict__ ck) {
    __shared__ float As[2][8][64];
    __shared__ float Bs[2][8][128];
    int blk = blockIdx.x;
    if (blk < 256) {
        gemm64x128_body(hs, Wq, q, Ee, Ee, (blk >> 3) * 64, (blk & 7) * 128, As, Bs);
    } else if (blk < 384) {
        int b = blk - 256;
        gemm64x128_body(hs, Wkv, kv, 2 * EKVv, Ee, (b >> 2) * 64, (b & 3) * 128, As, Bs);
    } else if (blk < 640) {
        int b = blk - 384;
        skinny_body(pe, Wpos, tk, EKVv, Ee, b >> 1, (b & 1) * 128);
    } else {
        int b = blk - 640;
        skinny_body(ce, Wchan, ck, EKVv, Ee, b >> 1, (b & 1) * 128);
    }
}

// ---------------- standalone GEMM for the output projection ------------------
__global__ __launch_bounds__(128) void sgemm128(
        const float* __restrict__ A, const float* __restrict__ B,
        float* __restrict__ Cmat, int N, int K) {
    __shared__ float As[2][8][64];
    __shared__ float Bs[2][8][128];
    gemm64x128_body(A, B, Cmat, N, K, blockIdx.y * 64, blockIdx.x * 128, As, Bs);
}

// ---------------- merged time_att + chan_att ---------------------------------
__global__ __launch_bounds__(256) void rel_att_kernel(
        const float* __restrict__ q, const float* __restrict__ bias) {
    __shared__ float qs[32][65];
    __shared__ float ks[128][64];
    int blk = blockIdx.x;
    int tid = threadIdx.x;
    if (blk < 1024) {
        int bh = blk & 31;
        int b = bh / Hh, h = bh % Hh, kvh = h / Gg;
        int t0 = (blk >> 5) * 32;
        for (int i = tid; i < 32 * 64; i += 256) {
            int r = i >> 6, d = i & 63;
            qs[r][d] = q[((size_t)(b * Tt + t0 + r)) * Ee + h * Dd + d]
                     + bias[EKVv + kvh * Dd + d];
        }
        for (int i = tid; i < 128 * 64; i += 256) {
            int p = i >> 6, d = i & 63;
            ks[p][d] = g_tk[p * EKVv + kvh * Dd + d];
        }
        __syncthreads();
        int r = tid & 31;
        int pb = (tid >> 5) * 16;
        float acc[16];
#pragma unroll
        for (int j = 0; j < 16; j++) acc[j] = 0.f;
        for (int d = 0; d < 64; d++) {
            float qv = qs[r][d];
#pragma unroll
            for (int j = 0; j < 16; j++) acc[j] += qv * ks[pb + j][d];
        }
        float* dst = g_time + ((size_t)bh * Tt + t0 + r) * Pp + pb;
#pragma unroll
        for (int j = 0; j < 16; j++) dst[j] = acc[j];
    } else {
        int bc = blk - 1024;
        int bh = bc & 31;
        int b = bh / Hh, h = bh % Hh, kvh = h / Gg;
        int t0 = (bc >> 5) * 32;
        for (int i = tid; i < 32 * 64; i += 256) {
            int r = i >> 6, d = i & 63;
            qs[r][d] = q[((size_t)(b * Tt + t0 + r)) * Ee + h * Dd + d]
                     + bias[2 * EKVv + kvh * Dd + d];
        }
        for (int i = tid; i < 8 * 64; i += 256) {
            int c = i >> 6, d = i & 63;
            ks[c][d] = g_ck[c * EKVv + kvh * Dd + d];
        }
        __syncthreads();
        int r = tid >> 3, c = tid & 7;
        float acc = 0.f;
#pragma unroll
        for (int d = 0; d < 64; d++) acc += qs[r][d] * ks[c][d];
        g_chan[((size_t)bh * Tt + t0 + r) * Cc + c] = acc;
    }
}

// ---------------- attention core: one block per (b, h, pt) -------------------
// lgT is TRANSPOSED: lgT[s][c] (c contiguous) -> broadcast LDS in v-phase.
__global__ __launch_bounds__(256) void attn_kernel(
        const float* __restrict__ q, const float* __restrict__ bias) {
    __shared__ float qg[8][68];
    __shared__ __align__(16) float lgT[1024][8];
    __shared__ float rinv[8];
    __shared__ __align__(16) float upool[128 * 68];   // gks / sred union
    float (*gks)[68] = (float(*)[68])upool;           // [128][68]
    float (*sred)[8][64] = (float(*)[8][64])upool;    // [8][8][64]

    int blk = blockIdx.x;
    int pt = (Pp - 1) - (blk % Pp);              // big-S blocks first
    int h  = (blk / Pp) % Hh;
    int b  = blk / (Pp * Hh);
    int kvh = h / Gg;
    int tid = threadIdx.x;
    int t0 = pt * Cc;

    for (int i = tid; i < 8 * 64; i += 256) {
        int c = i >> 6, d = i & 63;
        qg[c][d] = q[((size_t)(b * Tt + t0 + c)) * Ee + h * Dd + d]
                 + bias[kvh * Dd + d];
    }
    __syncthreads();

    int S = (pt + 1) * Cc;
    const float* tbase = g_time + (size_t)(b * Hh + h) * Tt * Pp;
    const float* cbase = g_chan + (size_t)(b * Hh + h) * Tt * Cc;

    // base logits, s-fastest: coalesced tbase gather, vector lgT stores
    for (int s0 = tid; s0 < S; s0 += 256) {
        int ps = s0 >> 3, cs = s0 & 7;
        float vals[8];
#pragma unroll
        for (int c = 0; c < 8; c++) {
            int t = t0 + c;
            unsigned m = (unsigned)(t + 1) * Pp + ps;
            unsigned i2 = m / (Tt + 1);
            float tv = 0.f;
            if (m - i2 * (Tt + 1) != 0) tv = tbase[m - i2 - 1];
            int dc = c - cs; dc = dc < 0 ? -dc : dc;
            vals[c] = tv + cbase[t * Cc + (Cc - 1 - dc)];
        }
        *(float4*)&lgT[s0][0] = make_float4(vals[0], vals[1], vals[2], vals[3]);
        *(float4*)&lgT[s0][4] = make_float4(vals[4], vals[5], vals[6], vals[7]);
    }
    __syncthreads();

    // global band: stage gk rows through smem (each row fetched once)
    int gLow = (pt == Pp - 1) ? 0 : ((pt > 10 ? pt - 10 : 0) * Cc);
    for (int sb = gLow; sb < S; sb += 128) {
        int rows = min(128, S - sb);
        for (int i = tid; i < rows * 16; i += 256) {
            int r = i >> 4, u = i & 15;
            const float4* src = (const float4*)(g_kv
                + ((size_t)(b * Tt + sb + r)) * (2 * EKVv) + kvh * Dd);
            *(float4*)&gks[r][u * 4] = src[u];
        }
        __syncthreads();
        for (int idx = tid; idx < rows * 8; idx += 256) {
            int r = idx >> 3, c = idx & 7;
            float acc = 0.f;
#pragma unroll
            for (int d4 = 0; d4 < 16; d4++) {
                float4 gv = *(const float4*)&gks[r][d4 * 4];
                float4 qv = *(const float4*)&qg[c][d4 * 4];
                acc += qv.x * gv.x + qv.y * gv.y + qv.z * gv.z + qv.w * gv.w;
            }
            lgT[sb + r][c] += acc;
        }
        __syncthreads();
    }

    // softmax: warp w owns channel row w (reads lgT[s][w])
    int w = tid >> 5, lane = tid & 31;
    {
        float mx = -1e30f;
        for (int s = lane; s < S; s += 32) mx = fmaxf(mx, lgT[s][w] * 0.125f);
#pragma unroll
        for (int o = 16; o > 0; o >>= 1)
            mx = fmaxf(mx, __shfl_xor_sync(0xffffffffu, mx, o));
        float sum = 0.f;
        for (int s = lane; s < S; s += 32) {
            float e = __expf(lgT[s][w] * 0.125f - mx);
            lgT[s][w] = e;
            sum += e;
        }
#pragma unroll
        for (int o = 16; o > 0; o >>= 1)
            sum += __shfl_xor_sync(0xffffffffu, sum, o);
        if (lane == 0) rinv[w] = 1.f / sum;
    }
    __syncthreads();

    // v-phase: thread = (sgroup, d-pair); packed-c FMA2, broadcast lgT reads
    {
        int dp = (tid & 31) * 2;
        int sg = tid >> 5;
        const float* vbase = g_kv + (size_t)b * Tt * (2 * EKVv) + EKVv
                           + kvh * Dd + dp;
        unsigned long long accp[2][4];   // [x/y][c-pair]
#pragma unroll
        for (int xy = 0; xy < 2; xy++)
#pragma unroll
            for (int j = 0; j < 4; j++) accp[xy][j] = 0ull;
        for (int s = sg; s < S; s += 8) {
            float2 vv = *(const float2*)(vbase + (size_t)s * (2 * EKVv));
            unsigned long long vx = dup2(vv.x), vy = dup2(vv.y);
            ulonglong2 wA = *(const ulonglong2*)&lgT[s][0];  // (w0,w1),(w2,w3)
            ulonglong2 wB = *(const ulonglong2*)&lgT[s][4];  // (w4,w5),(w6,w7)
            fma2(accp[0][0], wA.x, vx); fma2(accp[1][0], wA.x, vy);
            fma2(accp[0][1], wA.y, vx); fma2(accp[1][1], wA.y, vy);
            fma2(accp[0][2], wB.x, vx); fma2(accp[1][2], wB.x, vy);
            fma2(accp[0][3], wB.y, vx); fma2(accp[1][3], wB.y, vy);
        }
#pragma unroll
        for (int j = 0; j < 4; j++) {
            float x0, x1, y0, y1;
            unpack2(accp[0][j], x0, x1);
            unpack2(accp[1][j], y0, y1);
            sred[sg][2 * j + 0][dp]     = x0;
            sred[sg][2 * j + 1][dp]     = x1;
            sred[sg][2 * j + 0][dp + 1] = y0;
            sred[sg][2 * j + 1][dp + 1] = y1;
        }
    }
    __syncthreads();
    for (int i = tid; i < 512; i += 256) {
        int c = i >> 6, dd = i & 63;
        float o = ((sred[0][c][dd] + sred[1][c][dd])
                 + (sred[2][c][dd] + sred[3][c][dd]))
                + ((sred[4][c][dd] + sred[5][c][dd])
                 + (sred[6][c][dd] + sred[7][c][dd]));
        g_ao[((size_t)(b * Tt + t0 + c)) * Ee + h * Dd + dd] = o * rinv[c];
    }
}

// ---------------- launch ----------------------------------------------------
extern "C" void kernel_launch(void* const* d_in, const int* in_sizes, int n_in,
                              void* d_out, int out_size) {
    const float* hs    = (const float*)d_in[0];
    const float* pe    = (const float*)d_in[1];
    const float* ce    = (const float*)d_in[2];
    const float* Wq    = (const float*)d_in[3];
    const float* Wkv   = (const float*)d_in[4];
    const float* Wpos  = (const float*)d_in[5];
    const float* Wchan = (const float*)d_in[6];
    const float* Wproj = (const float*)d_in[7];
    const float* bias  = (const float*)d_in[8];

    float *q, *kv, *tk, *ck, *ao;
    cudaGetSymbolAddress((void**)&q,  g_q);
    cudaGetSymbolAddress((void**)&kv, g_kv);
    cudaGetSymbolAddress((void**)&tk, g_tk);
    cudaGetSymbolAddress((void**)&ck, g_ck);
    cudaGetSymbolAddress((void**)&ao, g_ao);

    // all projections in one chip-filling launch
    mega_gemm<<<656, 128>>>(hs, Wq, Wkv, pe, Wpos, ce, Wchan, q, kv, tk, ck);

    // relative logits (time + chan merged)
    rel_att_kernel<<<2048, 256>>>(q, bias);

    // attention core
    attn_kernel<<<Bb * Hh * Pp, 256>>>(q, bias);

    // output projection -> d_out
    sgemm128<<<dim3(Ee / 128, (Bb * Tt) / 64), 128>>>(ao, Wproj, (float*)d_out, Ee, Ee);
}